// round 2
// baseline (speedup 1.0000x reference)
#include <cuda_runtime.h>
#include <cstdint>

// ---------------------------------------------------------------------------
// SparseGraphLearn: h = X @ W  (M x 256 @ 256 x 128), then per-edge
// ew[e] = relu( sum_j |h[u][j]-h[v][j]| * a[j] )
// Output layout: [ h (M*128 floats) | edge_weight (E floats) ]
// ---------------------------------------------------------------------------

#define IN_F  256
#define OUT_F 128

// ---------------- GEMM: TF32 mma.sync m16n8k8, 128x128 CTA tile ------------
#define BM 128
#define BK 32
#define ASTRIDE 36   // == 4 mod 32 -> conflict-free A fragment loads
#define BSTRIDE 136  // == 8 mod 32 -> conflict-free B fragment loads

__device__ __forceinline__ uint32_t f2tf32(float x) {
    uint32_t y;
    asm("cvt.rna.tf32.f32 %0, %1;" : "=r"(y) : "f"(x));
    return y;
}

__device__ __forceinline__ void mma_tf32(float c[4], const uint32_t a[4], const uint32_t b[2]) {
    asm volatile(
        "mma.sync.aligned.m16n8k8.row.col.f32.tf32.tf32.f32 "
        "{%0,%1,%2,%3}, {%4,%5,%6,%7}, {%8,%9}, {%0,%1,%2,%3};\n"
        : "+f"(c[0]), "+f"(c[1]), "+f"(c[2]), "+f"(c[3])
        : "r"(a[0]), "r"(a[1]), "r"(a[2]), "r"(a[3]), "r"(b[0]), "r"(b[1]));
}

__global__ __launch_bounds__(256) void gemm_tf32_kernel(
    const float* __restrict__ A,   // [M, 256]
    const float* __restrict__ W,   // [256, 128]
    float* __restrict__ C,         // [M, 128]
    int M)
{
    __shared__ uint32_t As[BM * ASTRIDE];  // 18432 B
    __shared__ uint32_t Bs[BK * BSTRIDE];  // 17408 B

    const int tid  = threadIdx.x;
    const int wid  = tid >> 5;
    const int lane = tid & 31;
    const int g    = lane >> 2;   // group 0..7
    const int t4   = lane & 3;    // 0..3
    const int wm   = wid >> 1;    // 0..3  (warp M tile of 32)
    const int wn   = wid & 1;     // 0..1  (warp N tile of 64)
    const int m0   = blockIdx.x * BM;

    float acc[2][8][4];
#pragma unroll
    for (int i = 0; i < 2; i++)
#pragma unroll
        for (int j = 0; j < 8; j++)
#pragma unroll
            for (int k = 0; k < 4; k++) acc[i][j][k] = 0.f;

    for (int kb = 0; kb < IN_F; kb += BK) {
        // Stage A tile: 128 rows x 32 cols (float4-coalesced)
#pragma unroll
        for (int i = 0; i < 4; i++) {
            int idx = tid + i * 256;          // 0..1023
            int r = idx >> 3;                 // 0..127
            int c = (idx & 7) * 4;            // 0,4,...,28
            float4 v = make_float4(0.f, 0.f, 0.f, 0.f);
            if (m0 + r < M)
                v = *reinterpret_cast<const float4*>(A + (size_t)(m0 + r) * IN_F + kb + c);
            uint32_t* dst = &As[r * ASTRIDE + c];
            dst[0] = f2tf32(v.x); dst[1] = f2tf32(v.y);
            dst[2] = f2tf32(v.z); dst[3] = f2tf32(v.w);
        }
        // Stage B tile: 32 rows x 128 cols
#pragma unroll
        for (int i = 0; i < 4; i++) {
            int idx = tid + i * 256;          // 0..1023
            int r = idx >> 5;                 // 0..31
            int c = (idx & 31) * 4;           // 0..124
            float4 v = *reinterpret_cast<const float4*>(W + (size_t)(kb + r) * OUT_F + c);
            uint32_t* dst = &Bs[r * BSTRIDE + c];
            dst[0] = f2tf32(v.x); dst[1] = f2tf32(v.y);
            dst[2] = f2tf32(v.z); dst[3] = f2tf32(v.w);
        }
        __syncthreads();

#pragma unroll
        for (int kk = 0; kk < BK; kk += 8) {
            uint32_t af[2][4];
#pragma unroll
            for (int mt = 0; mt < 2; mt++) {
                int r0 = wm * 32 + mt * 16 + g;
                af[mt][0] = As[(r0)     * ASTRIDE + kk + t4];
                af[mt][1] = As[(r0 + 8) * ASTRIDE + kk + t4];
                af[mt][2] = As[(r0)     * ASTRIDE + kk + t4 + 4];
                af[mt][3] = As[(r0 + 8) * ASTRIDE + kk + t4 + 4];
            }
            uint32_t bf[8][2];
#pragma unroll
            for (int nt = 0; nt < 8; nt++) {
                int cn = wn * 64 + nt * 8 + g;
                bf[nt][0] = Bs[(kk + t4)     * BSTRIDE + cn];
                bf[nt][1] = Bs[(kk + t4 + 4) * BSTRIDE + cn];
            }
#pragma unroll
            for (int mt = 0; mt < 2; mt++)
#pragma unroll
                for (int nt = 0; nt < 8; nt++)
                    mma_tf32(acc[mt][nt], af[mt], bf[nt]);
        }
        __syncthreads();
    }

    // Epilogue: float2 stores (c0,c1) and (c2,c3) are adjacent columns
#pragma unroll
    for (int mt = 0; mt < 2; mt++) {
#pragma unroll
        for (int nt = 0; nt < 8; nt++) {
            int r0 = m0 + wm * 32 + mt * 16 + g;
            int cn = wn * 64 + nt * 8 + t4 * 2;
            if (r0 < M)
                *reinterpret_cast<float2*>(C + (size_t)r0 * OUT_F + cn) =
                    make_float2(acc[mt][nt][0], acc[mt][nt][1]);
            if (r0 + 8 < M)
                *reinterpret_cast<float2*>(C + (size_t)(r0 + 8) * OUT_F + cn) =
                    make_float2(acc[mt][nt][2], acc[mt][nt][3]);
        }
    }
}

// ---------------- Edge-index dtype detection (int32 vs int64) --------------
// JAX with default x64-disabled silently downcasts jnp.int64 -> int32, so the
// edge tensor's true dtype is ambiguous. For little-endian int64 values
// < 2^31, every odd 32-bit word is zero; for random int32 indices in
// [0, 100000) the probability all 8 sampled odd words are zero is ~1e-40.
__device__ int g_edge_is_i64;

__global__ void detect_edge_dtype_kernel(const int* __restrict__ edge_words) {
    int i64 = 1;
#pragma unroll
    for (int i = 1; i < 16; i += 2)
        if (edge_words[i] != 0) i64 = 0;
    g_edge_is_i64 = i64;
}

// ---------------- Edge phase: warp per edge, L2-resident gather ------------
__global__ __launch_bounds__(256) void edge_kernel(
    const float* __restrict__ h,
    const void* __restrict__ edge,        // [2, E] int32 or int64
    const float* __restrict__ a,          // [128]
    float* __restrict__ out,              // [E]
    int E)
{
    int gw   = (int)((blockIdx.x * 256u + threadIdx.x) >> 5);
    int lane = threadIdx.x & 31;
    if (gw >= E) return;

    int u, v;
    if (g_edge_is_i64) {
        const long long* e = (const long long*)edge;
        u = (int)e[gw];
        v = (int)e[(size_t)E + gw];
    } else {
        const int* e = (const int*)edge;
        u = e[gw];
        v = e[(size_t)E + gw];
    }

    float4 av = __ldg(reinterpret_cast<const float4*>(a) + lane);
    float4 x  = __ldg(reinterpret_cast<const float4*>(h + (size_t)u * OUT_F) + lane);
    float4 y  = __ldg(reinterpret_cast<const float4*>(h + (size_t)v * OUT_F) + lane);

    float s = fabsf(x.x - y.x) * av.x + fabsf(x.y - y.y) * av.y +
              fabsf(x.z - y.z) * av.z + fabsf(x.w - y.w) * av.w;

#pragma unroll
    for (int o = 16; o; o >>= 1) s += __shfl_xor_sync(0xFFFFFFFFu, s, o);

    if (lane == 0) out[gw] = fmaxf(s, 0.f);
}

// ---------------------------------------------------------------------------
extern "C" void kernel_launch(void* const* d_in, const int* in_sizes, int n_in,
                              void* d_out, int out_size)
{
    // Identify inputs by element count (robust to metadata ordering):
    //   a      -> 128 (OUT_F)
    //   weight -> 32768 (IN_F*OUT_F)
    //   inputs vs edge -> the two large ones; larger is inputs (M*256 vs 2*E)
    const float* X = nullptr;
    const void*  Ed = nullptr;
    const float* W = nullptr;
    const float* a = nullptr;
    int big_idx[2] = {-1, -1};
    int nbig = 0;
    for (int i = 0; i < n_in; i++) {
        long long s = in_sizes[i];
        if (s == OUT_F)                a = (const float*)d_in[i];
        else if (s == IN_F * OUT_F)    W = (const float*)d_in[i];
        else if (nbig < 2)             big_idx[nbig++] = i;
    }
    int xi = big_idx[0], ei = big_idx[1];
    if (in_sizes[xi] < in_sizes[ei]) { int t = xi; xi = ei; ei = t; }
    X  = (const float*)d_in[xi];
    Ed = d_in[ei];

    int M = in_sizes[xi] / IN_F;
    int E = in_sizes[ei] / 2;

    float* h  = (float*)d_out;                     // [M, 128]
    float* ew = (float*)d_out + (size_t)M * OUT_F; // [E]

    detect_edge_dtype_kernel<<<1, 1>>>((const int*)Ed);

    int gemm_blocks = (M + BM - 1) / BM;
    gemm_tf32_kernel<<<gemm_blocks, 256>>>(X, W, h, M);

    int warps_per_block = 256 / 32;
    int edge_blocks = (E + warps_per_block - 1) / warps_per_block;
    edge_kernel<<<edge_blocks, 256>>>(h, Ed, a, ew, E);
}